// round 1
// baseline (speedup 1.0000x reference)
#include <cuda_runtime.h>
#include <math.h>
#include <stdint.h>

// Problem constants
#define T_TOK 8192
#define D_IN  2048
#define N_QKV 4096
#define Hh    16
#define KVHh  8
#define DHh   128
#define Bb    4
#define Ll    2048
#define Cc    64

// Scratch (device globals: allocation-free per harness rules)
__device__ float g_q[(size_t)T_TOK * 2048];   // relu(q)*DH^-0.5, [T, H*DH]
__device__ float g_k[(size_t)T_TOK * 1024];   // min(sigmoid(k),0.95), [T, KVH*DH]
__device__ float g_g[(size_t)T_TOK * 1024];   // log1p(-k'), [T, KVH*DH]
__device__ float g_v[(size_t)T_TOK * 1024];   // v, [T, KVH*DH]

// ---------------- packed f32x2 helpers ----------------
__device__ __forceinline__ void ffma2(unsigned long long &d, unsigned long long a, unsigned long long b) {
    asm("fma.rn.f32x2 %0, %1, %2, %0;" : "+l"(d) : "l"(a), "l"(b));
}
__device__ __forceinline__ unsigned long long mul2(unsigned long long a, unsigned long long b) {
    unsigned long long d;
    asm("mul.rn.f32x2 %0, %1, %2;" : "=l"(d) : "l"(a), "l"(b));
    return d;
}
__device__ __forceinline__ unsigned long long pack2(float x) {
    unsigned long long r;
    unsigned int xi = __float_as_uint(x);
    asm("mov.b64 %0, {%1, %1};" : "=l"(r) : "r"(xi));
    return r;
}

// ---------------- Kernel 1: QKV GEMM + fused transforms ----------------
// X [8192,2048] @ W [2048,4096] + bias -> routed into g_q/g_k/g_g/g_v
__global__ __launch_bounds__(256) void qkv_gemm(const float* __restrict__ X,
                                                const float* __restrict__ W,
                                                const float* __restrict__ bias) {
    __shared__ float As[16][132];   // As[k][m]
    __shared__ float Bs[16][132];   // Bs[k][n]

    const int bm = blockIdx.y * 128;
    const int bn = blockIdx.x * 128;
    const int tid = threadIdx.x;
    const int ty = tid >> 4, tx = tid & 15;

    unsigned long long acc[8][4];
#pragma unroll
    for (int i = 0; i < 8; i++)
#pragma unroll
        for (int j = 0; j < 4; j++) acc[i][j] = 0ULL;

    const int lr = tid >> 2;                  // 0..63
    const int lc = (tid & 3) << 2;            // 0,4,8,12
    const float* Xp = X + (size_t)(bm + lr) * D_IN + lc;
    const int rb = tid >> 5;                  // 0..7
    const int cb = (tid & 31) << 2;           // 0..124
    const float* Wp = W + (size_t)rb * N_QKV + bn + cb;

    for (int k0 = 0; k0 < D_IN; k0 += 16) {
        float4 a0 = *(const float4*)(Xp + k0);
        float4 a1 = *(const float4*)(Xp + (size_t)64 * D_IN + k0);
        float4 b0 = *(const float4*)(Wp + (size_t)k0 * N_QKV);
        float4 b1 = *(const float4*)(Wp + (size_t)(k0 + 8) * N_QKV);

        As[lc + 0][lr] = a0.x; As[lc + 1][lr] = a0.y; As[lc + 2][lr] = a0.z; As[lc + 3][lr] = a0.w;
        As[lc + 0][lr + 64] = a1.x; As[lc + 1][lr + 64] = a1.y; As[lc + 2][lr + 64] = a1.z; As[lc + 3][lr + 64] = a1.w;
        *(float4*)&Bs[rb][cb]     = b0;
        *(float4*)&Bs[rb + 8][cb] = b1;
        __syncthreads();

#pragma unroll
        for (int kk = 0; kk < 16; kk++) {
            float4 am0 = *(const float4*)&As[kk][ty * 8];
            float4 am1 = *(const float4*)&As[kk][ty * 8 + 4];
            const unsigned long long* brow = (const unsigned long long*)&Bs[kk][tx * 8];
            unsigned long long bv0 = brow[0], bv1 = brow[1], bv2 = brow[2], bv3 = brow[3];
            unsigned long long pa[8];
            pa[0] = pack2(am0.x); pa[1] = pack2(am0.y); pa[2] = pack2(am0.z); pa[3] = pack2(am0.w);
            pa[4] = pack2(am1.x); pa[5] = pack2(am1.y); pa[6] = pack2(am1.z); pa[7] = pack2(am1.w);
#pragma unroll
            for (int i = 0; i < 8; i++) {
                ffma2(acc[i][0], pa[i], bv0);
                ffma2(acc[i][1], pa[i], bv1);
                ffma2(acc[i][2], pa[i], bv2);
                ffma2(acc[i][3], pa[i], bv3);
            }
        }
        __syncthreads();
    }

    // Epilogue: bias + route with fused nonlinearities
    const int m0 = bm + ty * 8;
    const int n0 = bn + tx * 8;
#pragma unroll
    for (int i = 0; i < 8; i++) {
        const size_t row = (size_t)(m0 + i);
#pragma unroll
        for (int j = 0; j < 4; j++) {
            float2 f = *(float2*)&acc[i][j];
            const int na = n0 + j * 2;
#pragma unroll
            for (int t = 0; t < 2; t++) {
                const int n = na + t;
                float val = (t == 0 ? f.x : f.y) + bias[n];
                if (n < 2048) {
                    g_q[row * 2048 + n] = fmaxf(val, 0.f) * 0.08838834764831845f; // DH^-0.5
                } else if (n < 3072) {
                    const int c = n - 2048;
                    float s = 1.f / (1.f + expf(-val));
                    s = fminf(s, 0.95f);
                    g_k[row * 1024 + c] = s;
                    g_g[row * 1024 + c] = log1pf(-s);
                } else {
                    g_v[row * 1024 + (n - 3072)] = val;
                }
            }
        }
    }
}

// ---------------- Kernel 2: chunked GLA scan ----------------
#define PQ 129   // padding for column-accessed 128-wide arrays
#define PV 68    // padding for row-vector-accessed 64-wide arrays

// smem layout sizes (floats)
#define SM_S   (128 * PV)        // 8704
#define SM_QKG (64 * PQ)         // 8256
#define SM_VA  (64 * PV)         // 4352
#define SMEM_FLOATS (SM_S + 3 * SM_QKG + 2 * SM_VA + 3 * 128)
#define SMEM_BYTES  (SMEM_FLOATS * 4)

__global__ __launch_bounds__(256) void gla_attn(const float* __restrict__ kvc,
                                                const int* __restrict__ sidx,
                                                float* __restrict__ out) {
    extern __shared__ float sm[];
    float* sS   = sm;                       // S[k][v]       128 x PV
    float* sQe  = sS + SM_S;                // g->Bc->q*e^Bc 64 x PQ
    float* sQe2 = sQe + SM_QKG;             // q*e^(Bc-R)    64 x PQ
    float* sKd  = sQe2 + SM_QKG;            // k*e^(R-Bc)    64 x PQ
    float* sV   = sKd + SM_QKG;             // v tile        64 x PV
    float* sA   = sV + SM_VA;               // A tile        64 x PV
    float* s_eR = sA + SM_VA;               // e^R           128
    float* s_fb = s_eR + 128;               // e^(blast - R) 128
    float* s_R  = s_fb + 128;               // R             128

    const int vh  = blockIdx.x;   // 0..1 (v half)
    const int h   = blockIdx.y;   // 0..15
    const int b   = blockIdx.z;   // 0..3
    const int kvh = h >> 1;       // repeat factor 2
    const int tid = threadIdx.x;
    const int ty = tid >> 4, tx = tid & 15;

    // init S from kv_cache[state_indices[b]][h][:, vh*64 : vh*64+64]
    {
        const int slot = sidx[b];
        const float* Sg = kvc + ((size_t)slot * Hh + h) * DHh * DHh + vh * 64;
        for (int idx = tid; idx < 128 * 64; idx += 256) {
            const int k = idx >> 6, v = idx & 63;
            sS[k * PV + v] = Sg[(size_t)k * DHh + v];
        }
    }
    __syncthreads();

    const float* qbase = g_q + (size_t)b * Ll * 2048 + h * DHh;
    const float* kbase = g_k + (size_t)b * Ll * 1024 + kvh * DHh;
    const float* gbase = g_g + (size_t)b * Ll * 1024 + kvh * DHh;
    const float* vbase = g_v + (size_t)b * Ll * 1024 + kvh * DHh + vh * 64;
    float* obase = out + (size_t)b * Ll * 2048 + h * DHh + vh * 64;

    for (int ch = 0; ch < 32; ch++) {
        const size_t row0 = (size_t)ch * 64;

        // --- load q, k', g (64x128) and v (64x64) ---
#pragma unroll
        for (int it = 0; it < 8; it++) {
            const int idx4 = tid + it * 256;
            const int r = idx4 >> 5;
            const int c4 = (idx4 & 31) << 2;
            float4 qv = *(const float4*)(qbase + (row0 + r) * 2048 + c4);
            float4 kv = *(const float4*)(kbase + (row0 + r) * 1024 + c4);
            float4 gv = *(const float4*)(gbase + (row0 + r) * 1024 + c4);
            float* qd = &sQe2[r * PQ + c4];
            qd[0] = qv.x; qd[1] = qv.y; qd[2] = qv.z; qd[3] = qv.w;
            float* kd = &sKd[r * PQ + c4];
            kd[0] = kv.x; kd[1] = kv.y; kd[2] = kv.z; kd[3] = kv.w;
            float* gd = &sQe[r * PQ + c4];
            gd[0] = gv.x; gd[1] = gv.y; gd[2] = gv.z; gd[3] = gv.w;
        }
#pragma unroll
        for (int it = 0; it < 4; it++) {
            const int idx4 = tid + it * 256;
            const int r = idx4 >> 4;
            const int c4 = (idx4 & 15) << 2;
            float4 vv = *(const float4*)(vbase + (row0 + r) * 1024 + c4);
            *(float4*)&sV[r * PV + c4] = vv;
        }
        __syncthreads();

        // --- cumsum g over chunk positions (per k-dim) ---
        if (tid < 128) {
            float a = sQe[tid];
            for (int i = 1; i < 64; i++) {
                a += sQe[i * PQ + tid];
                sQe[i * PQ + tid] = a;
            }
            const float R = sQe[31 * PQ + tid];
            s_R[tid]  = R;
            s_eR[tid] = __expf(R);
            s_fb[tid] = __expf(a - R);   // a == Bc[63] == b_last
        }
        __syncthreads();

        // --- per-element exponential scalings ---
        for (int idx = tid; idx < 64 * 128; idx += 256) {
            const int i = idx >> 7, k = idx & 127;
            const int o_ = i * PQ + k;
            const float bc = sQe[o_];
            const float R  = s_R[k];
            const float e1 = __expf(fminf(bc - R, 80.f));   // e^(Bc-R)
            const float e2 = __expf(fminf(R - bc, 80.f));   // e^(R-Bc)
            const float q  = sQe2[o_];
            sQe2[o_] = q * e1;                 // q*e^(Bc-R)
            sQe[o_]  = q * e1 * s_eR[k];       // q*e^Bc
            sKd[o_] *= e2;                     // k*e^(R-Bc)
        }
        __syncthreads();

        const int i0 = ty * 4, v0 = tx * 4, j0 = tx * 4;

        // --- GEMM1: o = (q*e^Bc) @ S  (64x64x128) ---
        unsigned long long oacc[4][2];
#pragma unroll
        for (int r = 0; r < 4; r++) { oacc[r][0] = 0ULL; oacc[r][1] = 0ULL; }
#pragma unroll 4
        for (int k = 0; k < 128; k++) {
            const unsigned long long s0 = *(const unsigned long long*)&sS[k * PV + v0];
            const unsigned long long s1 = *(const unsigned long long*)&sS[k * PV + v0 + 2];
#pragma unroll
            for (int r = 0; r < 4; r++) {
                const unsigned long long pa = pack2(sQe[(i0 + r) * PQ + k]);
                ffma2(oacc[r][0], pa, s0);
                ffma2(oacc[r][1], pa, s1);
            }
        }

        // --- GEMM2: A = Qe2 @ Kd^T  (64x64x128), then causal mask ---
        float aacc[4][4];
#pragma unroll
        for (int r = 0; r < 4; r++)
#pragma unroll
            for (int c = 0; c < 4; c++) aacc[r][c] = 0.f;
#pragma unroll 2
        for (int k = 0; k < 128; k++) {
            float av[4], bv[4];
#pragma unroll
            for (int r = 0; r < 4; r++) av[r] = sQe2[(i0 + r) * PQ + k];
#pragma unroll
            for (int c = 0; c < 4; c++) bv[c] = sKd[(j0 + c) * PQ + k];
#pragma unroll
            for (int r = 0; r < 4; r++)
#pragma unroll
                for (int c = 0; c < 4; c++) aacc[r][c] = fmaf(av[r], bv[c], aacc[r][c]);
        }
#pragma unroll
        for (int r = 0; r < 4; r++)
#pragma unroll
            for (int c = 0; c < 4; c++)
                sA[(i0 + r) * PV + (j0 + c)] = (j0 + c <= i0 + r) ? aacc[r][c] : 0.f;
        __syncthreads();

        // --- rescale Kd -> kg = k*e^(b_last - Bc) ---
        for (int idx = tid; idx < 64 * 128; idx += 256) {
            const int k = idx & 127;
            sKd[(idx >> 7) * PQ + k] *= s_fb[k];
        }

        // --- GEMM3: o += A @ V  (64x64x64) ---
#pragma unroll 4
        for (int j = 0; j < 64; j++) {
            const unsigned long long vv0 = *(const unsigned long long*)&sV[j * PV + v0];
            const unsigned long long vv1 = *(const unsigned long long*)&sV[j * PV + v0 + 2];
#pragma unroll
            for (int r = 0; r < 4; r++) {
                const unsigned long long pa = pack2(sA[(i0 + r) * PV + j]);
                ffma2(oacc[r][0], pa, vv0);
                ffma2(oacc[r][1], pa, vv1);
            }
        }

        // --- write output tile ---
#pragma unroll
        for (int r = 0; r < 4; r++) {
            float2 x0 = *(float2*)&oacc[r][0];
            float2 x1 = *(float2*)&oacc[r][1];
            float4 ov = make_float4(x0.x, x0.y, x1.x, x1.y);
            *(float4*)(obase + (row0 + i0 + r) * 2048 + v0) = ov;
        }
        __syncthreads();   // kg-rescale + output done; old-S reads done

        // --- state update: S = S*e^(b_last) + Kg^T @ V  (128x64x64) ---
        {
            const int k0 = (tid >> 4) * 8;
            const int vs = (tid & 15) * 4;
            unsigned long long su[8][2];
#pragma unroll
            for (int r = 0; r < 8; r++) {
                const float ebl = s_eR[k0 + r] * s_fb[k0 + r];  // e^(b_last)
                const unsigned long long pe = pack2(ebl);
                const unsigned long long o0 = *(unsigned long long*)&sS[(k0 + r) * PV + vs];
                const unsigned long long o1 = *(unsigned long long*)&sS[(k0 + r) * PV + vs + 2];
                su[r][0] = mul2(pe, o0);
                su[r][1] = mul2(pe, o1);
            }
#pragma unroll 2
            for (int j = 0; j < 64; j++) {
                const unsigned long long vv0 = *(const unsigned long long*)&sV[j * PV + vs];
                const unsigned long long vv1 = *(const unsigned long long*)&sV[j * PV + vs + 2];
#pragma unroll
                for (int r = 0; r < 8; r++) {
                    const unsigned long long pk = pack2(sKd[j * PQ + k0 + r]);
                    ffma2(su[r][0], pk, vv0);
                    ffma2(su[r][1], pk, vv1);
                }
            }
#pragma unroll
            for (int r = 0; r < 8; r++) {
                *(unsigned long long*)&sS[(k0 + r) * PV + vs]     = su[r][0];
                *(unsigned long long*)&sS[(k0 + r) * PV + vs + 2] = su[r][1];
            }
        }
        __syncthreads();
    }
}

// ---------------- launch ----------------
extern "C" void kernel_launch(void* const* d_in, const int* in_sizes, int n_in,
                              void* d_out, int out_size) {
    const float* X    = (const float*)d_in[0];   // hidden_states [8192,2048]
    const float* W    = (const float*)d_in[1];   // W_qkv [2048,4096]
    const float* bias = (const float*)d_in[2];   // b_qkv [4096]
    const float* kvc  = (const float*)d_in[3];   // kv_cache [16,16,128,128]
    const int*   sidx = (const int*)d_in[4];     // state_indices [4]
    float* out = (float*)d_out;                  // [8192,2048]

    dim3 gg(N_QKV / 128, T_TOK / 128);
    qkv_gemm<<<gg, 256>>>(X, W, bias);

    cudaFuncSetAttribute(gla_attn, cudaFuncAttributeMaxDynamicSharedMemorySize, SMEM_BYTES);
    dim3 ga(2, Hh, Bb);
    gla_attn<<<ga, 256, SMEM_BYTES>>>(kvc, sidx, out);
}

// round 3
// speedup vs baseline: 1.9800x; 1.9800x over previous
#include <cuda_runtime.h>
#include <cuda_bf16.h>
#include <math.h>
#include <stdint.h>

// Problem constants
#define T_TOK 8192
#define D_IN  2048
#define N_QKV 4096
#define Hh    16
#define KVHh  8
#define DHh   128
#define Bb    4
#define Ll    2048
#define Cc    64

// Scratch (device globals: allocation-free per harness rules)
__device__ float g_q[(size_t)T_TOK * 2048];
__device__ float g_k[(size_t)T_TOK * 1024];
__device__ float g_g[(size_t)T_TOK * 1024];
__device__ float g_v[(size_t)T_TOK * 1024];
// bf16 split operands
__device__ __align__(1024) __nv_bfloat16 g_xbf[2ull * T_TOK * D_IN];   // [hv][8192][2048]
__device__ __align__(1024) __nv_bfloat16 g_wtbf[2ull * N_QKV * D_IN];  // [hv][4096][2048] (W^T)

// ================= helpers =================
__device__ __forceinline__ uint32_t smem_to_u32(const void* p) {
    uint32_t a;
    asm("{ .reg .u64 t; cvta.to.shared.u64 t, %1; cvt.u32.u64 %0, t; }" : "=r"(a) : "l"(p));
    return a;
}
__device__ __forceinline__ void cp16(uint32_t dst, const void* src) {
    asm volatile("cp.async.cg.shared.global [%0], [%1], 16;\n" :: "r"(dst), "l"(src));
}
__device__ __forceinline__ void cp_commit() { asm volatile("cp.async.commit_group;\n" ::: "memory"); }
__device__ __forceinline__ void ldsm4(uint32_t* r, uint32_t addr) {
    asm volatile("ldmatrix.sync.aligned.m8n8.x4.shared.b16 {%0,%1,%2,%3}, [%4];"
        : "=r"(r[0]), "=r"(r[1]), "=r"(r[2]), "=r"(r[3]) : "r"(addr));
}
__device__ __forceinline__ void mma_bf16(float* d, const uint32_t* a, const uint32_t* b) {
    asm volatile("mma.sync.aligned.m16n8k16.row.col.f32.bf16.bf16.f32 "
        "{%0,%1,%2,%3}, {%4,%5,%6,%7}, {%8,%9}, {%0,%1,%2,%3};"
        : "+f"(d[0]), "+f"(d[1]), "+f"(d[2]), "+f"(d[3])
        : "r"(a[0]), "r"(a[1]), "r"(a[2]), "r"(a[3]), "r"(b[0]), "r"(b[1]));
}

// ---------------- packed f32x2 helpers (for gla kernel) ----------------
__device__ __forceinline__ void ffma2(unsigned long long &d, unsigned long long a, unsigned long long b) {
    asm("fma.rn.f32x2 %0, %1, %2, %0;" : "+l"(d) : "l"(a), "l"(b));
}
__device__ __forceinline__ unsigned long long mul2(unsigned long long a, unsigned long long b) {
    unsigned long long d;
    asm("mul.rn.f32x2 %0, %1, %2;" : "=l"(d) : "l"(a), "l"(b));
    return d;
}
__device__ __forceinline__ unsigned long long pack2(float x) {
    unsigned long long r;
    unsigned int xi = __float_as_uint(x);
    asm("mov.b64 %0, {%1, %1};" : "=l"(r) : "r"(xi));
    return r;
}

// ================= Prep kernels =================
__global__ __launch_bounds__(256) void prep_x(const float* __restrict__ X) {
    size_t i = ((size_t)blockIdx.x * 256 + threadIdx.x) * 4;
    float4 x = *(const float4*)(X + i);
    __nv_bfloat162 h0 = __floats2bfloat162_rn(x.x, x.y);
    __nv_bfloat162 h1 = __floats2bfloat162_rn(x.z, x.w);
    float r0 = x.x - __low2float(h0), r1 = x.y - __high2float(h0);
    float r2 = x.z - __low2float(h1), r3 = x.w - __high2float(h1);
    __nv_bfloat162 l0 = __floats2bfloat162_rn(r0, r1);
    __nv_bfloat162 l1 = __floats2bfloat162_rn(r2, r3);
    __nv_bfloat162* hi = (__nv_bfloat162*)(g_xbf + i);
    __nv_bfloat162* lo = (__nv_bfloat162*)(g_xbf + (size_t)T_TOK * D_IN + i);
    hi[0] = h0; hi[1] = h1;
    lo[0] = l0; lo[1] = l1;
}

__global__ __launch_bounds__(256) void prep_w(const float* __restrict__ W) {
    __shared__ float t[32][33];
    const int n0 = blockIdx.x * 32;
    const int k0 = blockIdx.y * 32;
    const int tx = threadIdx.x & 31, ty = threadIdx.x >> 5;  // ty 0..7
#pragma unroll
    for (int r = 0; r < 32; r += 8)
        t[ty + r][tx] = W[(size_t)(k0 + ty + r) * N_QKV + n0 + tx];
    __syncthreads();
#pragma unroll
    for (int r = 0; r < 32; r += 8) {
        const int nl = ty + r;
        float x = t[tx][nl];   // W[k0+tx][n0+nl]
        __nv_bfloat16 h = __float2bfloat16_rn(x);
        __nv_bfloat16 l = __float2bfloat16_rn(x - __bfloat162float(h));
        const size_t o = (size_t)(n0 + nl) * D_IN + k0 + tx;
        g_wtbf[o] = h;
        g_wtbf[(size_t)N_QKV * D_IN + o] = l;
    }
}

// ================= Kernel 1: QKV GEMM (mma.sync bf16 split) =================
// Block tile M=128 x N=128, K-chunk=32. Stage: A[128][64]bf16 (hi cols 0-31,
// lo cols 32-63) + B[128][64]bf16, each row 128B -> SW128 swizzle. 3 stages.
#define NSTAGE  3
#define ATILE_B 16384
#define STAGE_B 32768
#define GEMM_SMEM (NSTAGE * STAGE_B)

__global__ __launch_bounds__(256) void qkv_gemm_mma(const float* __restrict__ bias) {
    extern __shared__ char smem[];
    const uint32_t sb = smem_to_u32(smem);
    const int tid = threadIdx.x;
    const int lane = tid & 31, wid = tid >> 5;
    const int bm = blockIdx.y * 128;
    const int bn = blockIdx.x * 128;
    const int mw = (wid >> 2) * 64;   // warp m offset within block
    const int nw = (wid & 3) * 32;    // warp n offset within block

    // --- stage loader: 2048 16B chunks, 8 per thread ---
    auto load_stage = [&](int c) {
        const uint32_t st = sb + (uint32_t)(c % NSTAGE) * STAGE_B;
        const int koff = c * 32;
#pragma unroll
        for (int i = 0; i < 8; i++) {
            const int u = tid + i * 256;          // 0..2047
            const int isB = u >> 10;              // 0: A, 1: B
            const int row = (u >> 3) & 127;
            const int unit = u & 7;               // 0-3 hi, 4-7 lo
            const int plane = unit >> 2, sub = unit & 3;
            const uint32_t dst = st + (uint32_t)isB * ATILE_B + row * 128 +
                                 (uint32_t)((unit ^ (row & 7)) << 4);
            const __nv_bfloat16* src = isB
                ? (g_wtbf + (size_t)plane * N_QKV * D_IN + (size_t)(bn + row) * D_IN + koff + sub * 8)
                : (g_xbf  + (size_t)plane * T_TOK * D_IN + (size_t)(bm + row) * D_IN + koff + sub * 8);
            cp16(dst, src);
        }
        cp_commit();
    };

    float acc[4][4][4];
#pragma unroll
    for (int i = 0; i < 4; i++)
#pragma unroll
        for (int j = 0; j < 4; j++)
#pragma unroll
            for (int t = 0; t < 4; t++) acc[i][j][t] = 0.f;

    // per-lane ldmatrix row parameters
    const int a_r  = mw + (lane & 15);
    const int a_rx = a_r & 7;
    const int ua_hi_base = (lane >> 4);                  // + kstep*2
    const int b_r  = nw + (lane & 7) + ((lane >> 4) << 3);
    const int b_rx = b_r & 7;
    const int ub_hi_base = ((lane >> 3) & 1);            // + kstep*2

    load_stage(0);
    load_stage(1);
    load_stage(2);

    for (int c = 0; c < 64; c++) {
        asm volatile("cp.async.wait_group 2;" ::: "memory");
        __syncthreads();

        const uint32_t st = sb + (uint32_t)(c % NSTAGE) * STAGE_B;
        const uint32_t stB = st + ATILE_B;
#pragma unroll
        for (int ks = 0; ks < 2; ks++) {
            const int ua = ks * 2 + ua_hi_base;   // hi unit for A
            const int ub = ks * 2 + ub_hi_base;   // hi unit for B
            uint32_t Ah[4][4], Al[4][4], Bh[2][4], Bl[2][4];
#pragma unroll
            for (int i = 0; i < 4; i++) {
                const uint32_t rowb = st + (uint32_t)(a_r + i * 16) * 128;
                ldsm4(Ah[i], rowb + (uint32_t)((ua ^ a_rx) << 4));
                ldsm4(Al[i], rowb + (uint32_t)(((ua + 4) ^ a_rx) << 4));
            }
#pragma unroll
            for (int p = 0; p < 2; p++) {
                const uint32_t rowb = stB + (uint32_t)(b_r + p * 16) * 128;
                ldsm4(Bh[p], rowb + (uint32_t)((ub ^ b_rx) << 4));
                ldsm4(Bl[p], rowb + (uint32_t)(((ub + 4) ^ b_rx) << 4));
            }
#pragma unroll
            for (int i = 0; i < 4; i++) {
#pragma unroll
                for (int j = 0; j < 4; j++) {
                    const uint32_t* bh = &Bh[j >> 1][(j & 1) * 2];
                    const uint32_t* bl = &Bl[j >> 1][(j & 1) * 2];
                    mma_bf16(acc[i][j], Ah[i], bh);   // hi*hi
                    mma_bf16(acc[i][j], Ah[i], bl);   // hi*lo
                    mma_bf16(acc[i][j], Al[i], bh);   // lo*hi
                }
            }
        }
        __syncthreads();
        if (c + 3 < 64) load_stage(c + 3);
    }

    // --- epilogue: bias + routed nonlinearities, straight from registers ---
    const int ml = bm + mw + (lane >> 2);
    const int nl0 = bn + nw + (lane & 3) * 2;
    const int region = (bn < 2048) ? 0 : (bn < 3072 ? 1 : 2);

#pragma unroll
    for (int j = 0; j < 4; j++) {
        const int n = nl0 + j * 8;
        const float b0 = __ldg(bias + n), b1 = __ldg(bias + n + 1);
#pragma unroll
        for (int i = 0; i < 4; i++) {
#pragma unroll
            for (int half = 0; half < 2; half++) {
                const int m = ml + i * 16 + half * 8;
                const float v0 = acc[i][j][half * 2 + 0] + b0;
                const float v1 = acc[i][j][half * 2 + 1] + b1;
                if (region == 0) {
                    float2 o = make_float2(fmaxf(v0, 0.f) * 0.08838834764831845f,
                                           fmaxf(v1, 0.f) * 0.08838834764831845f);
                    *(float2*)&g_q[(size_t)m * 2048 + n] = o;
                } else if (region == 1) {
                    const int cc = n - 2048;
                    float s0 = fminf(1.f / (1.f + expf(-v0)), 0.95f);
                    float s1 = fminf(1.f / (1.f + expf(-v1)), 0.95f);
                    *(float2*)&g_k[(size_t)m * 1024 + cc] = make_float2(s0, s1);
                    *(float2*)&g_g[(size_t)m * 1024 + cc] = make_float2(log1pf(-s0), log1pf(-s1));
                } else {
                    *(float2*)&g_v[(size_t)m * 1024 + (n - 3072)] = make_float2(v0, v1);
                }
            }
        }
    }
}

// ================= Kernel 2: chunked GLA scan =================
#define PQ 129
#define PV 68
#define SM_S   (128 * PV)
#define SM_QKG (64 * PQ)
#define SM_VA  (64 * PV)
#define SMEM_FLOATS (SM_S + 3 * SM_QKG + 2 * SM_VA + 3 * 128)
#define SMEM_BYTES  (SMEM_FLOATS * 4)

__global__ __launch_bounds__(256) void gla_attn(const float* __restrict__ kvc,
                                                const int* __restrict__ sidx,
                                                float* __restrict__ out) {
    extern __shared__ float sm[];
    float* sS   = sm;
    float* sQe  = sS + SM_S;
    float* sQe2 = sQe + SM_QKG;
    float* sKd  = sQe2 + SM_QKG;
    float* sV   = sKd + SM_QKG;
    float* sA   = sV + SM_VA;
    float* s_eR = sA + SM_VA;
    float* s_fb = s_eR + 128;
    float* s_R  = s_fb + 128;

    const int vh  = blockIdx.x;
    const int h   = blockIdx.y;
    const int b   = blockIdx.z;
    const int kvh = h >> 1;
    const int tid = threadIdx.x;
    const int ty = tid >> 4, tx = tid & 15;

    {
        const int slot = sidx[b];
        const float* Sg = kvc + ((size_t)slot * Hh + h) * DHh * DHh + vh * 64;
        for (int idx = tid; idx < 128 * 64; idx += 256) {
            const int k = idx >> 6, v = idx & 63;
            sS[k * PV + v] = Sg[(size_t)k * DHh + v];
        }
    }
    __syncthreads();

    const float* qbase = g_q + (size_t)b * Ll * 2048 + h * DHh;
    const float* kbase = g_k + (size_t)b * Ll * 1024 + kvh * DHh;
    const float* gbase = g_g + (size_t)b * Ll * 1024 + kvh * DHh;
    const float* vbase = g_v + (size_t)b * Ll * 1024 + kvh * DHh + vh * 64;
    float* obase = out + (size_t)b * Ll * 2048 + h * DHh + vh * 64;

    for (int ch = 0; ch < 32; ch++) {
        const size_t row0 = (size_t)ch * 64;

#pragma unroll
        for (int it = 0; it < 8; it++) {
            const int idx4 = tid + it * 256;
            const int r = idx4 >> 5;
            const int c4 = (idx4 & 31) << 2;
            float4 qv = *(const float4*)(qbase + (row0 + r) * 2048 + c4);
            float4 kv = *(const float4*)(kbase + (row0 + r) * 1024 + c4);
            float4 gv = *(const float4*)(gbase + (row0 + r) * 1024 + c4);
            float* qd = &sQe2[r * PQ + c4];
            qd[0] = qv.x; qd[1] = qv.y; qd[2] = qv.z; qd[3] = qv.w;
            float* kd = &sKd[r * PQ + c4];
            kd[0] = kv.x; kd[1] = kv.y; kd[2] = kv.z; kd[3] = kv.w;
            float* gd = &sQe[r * PQ + c4];
            gd[0] = gv.x; gd[1] = gv.y; gd[2] = gv.z; gd[3] = gv.w;
        }
#pragma unroll
        for (int it = 0; it < 4; it++) {
            const int idx4 = tid + it * 256;
            const int r = idx4 >> 4;
            const int c4 = (idx4 & 15) << 2;
            float4 vv = *(const float4*)(vbase + (row0 + r) * 1024 + c4);
            *(float4*)&sV[r * PV + c4] = vv;
        }
        __syncthreads();

        if (tid < 128) {
            float a = sQe[tid];
            for (int i = 1; i < 64; i++) {
                a += sQe[i * PQ + tid];
                sQe[i * PQ + tid] = a;
            }
            const float R = sQe[31 * PQ + tid];
            s_R[tid]  = R;
            s_eR[tid] = __expf(R);
            s_fb[tid] = __expf(a - R);
        }
        __syncthreads();

        for (int idx = tid; idx < 64 * 128; idx += 256) {
            const int i = idx >> 7, k = idx & 127;
            const int o_ = i * PQ + k;
            const float bc = sQe[o_];
            const float R  = s_R[k];
            const float e1 = __expf(fminf(bc - R, 80.f));
            const float e2 = __expf(fminf(R - bc, 80.f));
            const float q  = sQe2[o_];
            sQe2[o_] = q * e1;
            sQe[o_]  = q * e1 * s_eR[k];
            sKd[o_] *= e2;
        }
        __syncthreads();

        const int i0 = ty * 4, v0 = tx * 4, j0 = tx * 4;

        unsigned long long oacc[4][2];
#pragma unroll
        for (int r = 0; r < 4; r++) { oacc[r][0] = 0ULL; oacc[r][1] = 0ULL; }
#pragma unroll 4
        for (int k = 0; k < 128; k++) {
            const unsigned long long s0 = *(const unsigned long long*)&sS[k * PV + v0];
            const unsigned long long s1 = *(const unsigned long long*)&sS[k * PV + v0 + 2];
#pragma unroll
            for (int r = 0; r < 4; r++) {
                const unsigned long long pa = pack2(sQe[(i0 + r) * PQ + k]);
                ffma2(oacc[r][0], pa, s0);
                ffma2(oacc[r][1], pa, s1);
            }
        }

        float aacc[4][4];
#pragma unroll
        for (int r = 0; r < 4; r++)
#pragma unroll
            for (int c = 0; c < 4; c++) aacc[r][c] = 0.f;
#pragma unroll 2
        for (int k = 0; k < 128; k++) {
            float av[4], bv[4];
#pragma unroll
            for (int r = 0; r < 4; r++) av[r] = sQe2[(i0 + r) * PQ + k];
#pragma unroll
            for (int c = 0; c < 4; c++) bv[c] = sKd[(j0 + c) * PQ + k];
#pragma unroll
            for (int r = 0; r < 4; r++)
#pragma unroll
                for (int c = 0; c < 4; c++) aacc[r][c] = fmaf(av[r], bv[c], aacc[r][c]);
        }
#pragma unroll
        for (int r = 0; r < 4; r++)
#pragma unroll
            for (int c = 0; c < 4; c++)
                sA[(i0 + r) * PV + (j0 + c)] = (j0 + c <= i0 + r) ? aacc[r][c] : 0.f;
        __syncthreads();

        for (int idx = tid; idx < 64 * 128; idx += 256) {
            const int k = idx & 127;
            sKd[(idx >> 7) * PQ + k] *= s_fb[k];
        }

#pragma unroll 4
        for (int j = 0; j < 64; j++) {
            const unsigned long long vv0 = *(const unsigned long long*)&sV[j * PV + v0];
            const unsigned long long vv1 = *(const unsigned long long*)&sV[j * PV + v0 + 2];
#pragma unroll
            for (int r = 0; r < 4; r++) {
                const unsigned long long pa = pack2(sA[(i0 + r) * PV + j]);
                ffma2(oacc[r][0], pa, vv0);
                ffma2(oacc[r][1], pa, vv1);
            }
        }

#pragma unroll
        for (int r = 0; r < 4; r++) {
            float2 x0 = *(float2*)&oacc[r][0];
            float2 x1 = *(float2*)&oacc[r][1];
            float4 ov = make_float4(x0.x, x0.y, x1.x, x1.y);
            *(float4*)(obase + (row0 + i0 + r) * 2048 + v0) = ov;
        }
        __syncthreads();

        {
            const int k0 = (tid >> 4) * 8;
            const int vs = (tid & 15) * 4;
            unsigned long long su[8][2];
#pragma unroll
            for (int r = 0; r < 8; r++) {
                const float ebl = s_eR[k0 + r] * s_fb[k0 + r];
                const unsigned long long pe = pack2(ebl);
                const unsigned long long o0 = *(unsigned long long*)&sS[(k0 + r) * PV + vs];
                const unsigned long long o1 = *(unsigned long long*)&sS[(k0 + r) * PV + vs + 2];
                su[r][0] = mul2(pe, o0);
                su[r][1] = mul2(pe, o1);
            }
#pragma unroll 2
            for (int j = 0; j < 64; j++) {
                const unsigned long long vv0 = *(const unsigned long long*)&sV[j * PV + vs];
                const unsigned long long vv1 = *(const unsigned long long*)&sV[j * PV + vs + 2];
#pragma unroll
                for (int r = 0; r < 8; r++) {
                    const unsigned long long pk = pack2(sKd[j * PQ + k0 + r]);
                    ffma2(su[r][0], pk, vv0);
                    ffma2(su[r][1], pk, vv1);
                }
            }
#pragma unroll
            for (int r = 0; r < 8; r++) {
                *(unsigned long long*)&sS[(k0 + r) * PV + vs]     = su[r][0];
                *(unsigned long long*)&sS[(k0 + r) * PV + vs + 2] = su[r][1];
            }
        }
        __syncthreads();
    }
}

// ---------------- launch ----------------
extern "C" void kernel_launch(void* const* d_in, const int* in_sizes, int n_in,
                              void* d_out, int out_size) {
    const float* X    = (const float*)d_in[0];
    const float* W    = (const float*)d_in[1];
    const float* bias = (const float*)d_in[2];
    const float* kvc  = (const float*)d_in[3];
    const int*   sidx = (const int*)d_in[4];
    float* out = (float*)d_out;

    prep_x<<<(T_TOK * D_IN) / (256 * 4), 256>>>(X);
    prep_w<<<dim3(N_QKV / 32, D_IN / 32), 256>>>(W);

    cudaFuncSetAttribute(qkv_gemm_mma, cudaFuncAttributeMaxDynamicSharedMemorySize, GEMM_SMEM);
    dim3 gg(N_QKV / 128, T_TOK / 128);
    qkv_gemm_mma<<<gg, 256, GEMM_SMEM>>>(bias);

    cudaFuncSetAttribute(gla_attn, cudaFuncAttributeMaxDynamicSharedMemorySize, SMEM_BYTES);
    dim3 ga(2, Hh, Bb);
    gla_attn<<<ga, 256, SMEM_BYTES>>>(kvc, sidx, out);
}

// round 5
// speedup vs baseline: 2.7557x; 1.3918x over previous
#include <cuda_runtime.h>
#include <cuda_bf16.h>
#include <math.h>
#include <stdint.h>

// Problem constants
#define T_TOK 8192
#define D_IN  2048
#define N_QKV 4096
#define Hh    16
#define KVHh  8
#define DHh   128
#define Bb    4
#define Ll    2048
#define Cc    64

// Scratch (device globals: allocation-free per harness rules)
__device__ float g_q[(size_t)T_TOK * 2048];
__device__ float g_k[(size_t)T_TOK * 1024];
__device__ float g_g[(size_t)T_TOK * 1024];
__device__ float g_v[(size_t)T_TOK * 1024];
// bf16 split operands
__device__ __align__(1024) __nv_bfloat16 g_xbf[2ull * T_TOK * D_IN];   // [hv][8192][2048]
__device__ __align__(1024) __nv_bfloat16 g_wtbf[2ull * N_QKV * D_IN];  // [hv][4096][2048] (W^T)

// ================= helpers =================
__device__ __forceinline__ uint32_t smem_to_u32(const void* p) {
    uint32_t a;
    asm("{ .reg .u64 t; cvta.to.shared.u64 t, %1; cvt.u32.u64 %0, t; }" : "=r"(a) : "l"(p));
    return a;
}
__device__ __forceinline__ void cp16(uint32_t dst, const void* src) {
    asm volatile("cp.async.cg.shared.global [%0], [%1], 16;\n" :: "r"(dst), "l"(src));
}
__device__ __forceinline__ void cp_commit() { asm volatile("cp.async.commit_group;\n" ::: "memory"); }
__device__ __forceinline__ void ldsm4(uint32_t* r, uint32_t addr) {
    asm volatile("ldmatrix.sync.aligned.m8n8.x4.shared.b16 {%0,%1,%2,%3}, [%4];"
        : "=r"(r[0]), "=r"(r[1]), "=r"(r[2]), "=r"(r[3]) : "r"(addr));
}
__device__ __forceinline__ void ldsm4t(uint32_t* r, uint32_t addr) {
    asm volatile("ldmatrix.sync.aligned.m8n8.x4.trans.shared.b16 {%0,%1,%2,%3}, [%4];"
        : "=r"(r[0]), "=r"(r[1]), "=r"(r[2]), "=r"(r[3]) : "r"(addr));
}
__device__ __forceinline__ void mma_bf16(float* d, const uint32_t* a, const uint32_t* b) {
    asm volatile("mma.sync.aligned.m16n8k16.row.col.f32.bf16.bf16.f32 "
        "{%0,%1,%2,%3}, {%4,%5,%6,%7}, {%8,%9}, {%0,%1,%2,%3};"
        : "+f"(d[0]), "+f"(d[1]), "+f"(d[2]), "+f"(d[3])
        : "r"(a[0]), "r"(a[1]), "r"(a[2]), "r"(a[3]), "r"(b[0]), "r"(b[1]));
}
__device__ __forceinline__ uint32_t bfpack(float x, float y) {
    __nv_bfloat162 h = __floats2bfloat162_rn(x, y);
    return *(uint32_t*)&h;
}
__device__ __forceinline__ float2 bfunpack(uint32_t u) {
    return __bfloat1622float2(*(__nv_bfloat162*)&u);
}

// ================= Prep kernels =================
__global__ __launch_bounds__(256) void prep_x(const float* __restrict__ X) {
    size_t i = ((size_t)blockIdx.x * 256 + threadIdx.x) * 4;
    float4 x = *(const float4*)(X + i);
    __nv_bfloat162 h0 = __floats2bfloat162_rn(x.x, x.y);
    __nv_bfloat162 h1 = __floats2bfloat162_rn(x.z, x.w);
    float r0 = x.x - __low2float(h0), r1 = x.y - __high2float(h0);
    float r2 = x.z - __low2float(h1), r3 = x.w - __high2float(h1);
    __nv_bfloat162 l0 = __floats2bfloat162_rn(r0, r1);
    __nv_bfloat162 l1 = __floats2bfloat162_rn(r2, r3);
    __nv_bfloat162* hi = (__nv_bfloat162*)(g_xbf + i);
    __nv_bfloat162* lo = (__nv_bfloat162*)(g_xbf + (size_t)T_TOK * D_IN + i);
    hi[0] = h0; hi[1] = h1;
    lo[0] = l0; lo[1] = l1;
}

__global__ __launch_bounds__(256) void prep_w(const float* __restrict__ W) {
    __shared__ float t[32][33];
    const int n0 = blockIdx.x * 32;
    const int k0 = blockIdx.y * 32;
    const int tx = threadIdx.x & 31, ty = threadIdx.x >> 5;
#pragma unroll
    for (int r = 0; r < 32; r += 8)
        t[ty + r][tx] = W[(size_t)(k0 + ty + r) * N_QKV + n0 + tx];
    __syncthreads();
#pragma unroll
    for (int r = 0; r < 32; r += 8) {
        const int nl = ty + r;
        float x = t[tx][nl];
        __nv_bfloat16 h = __float2bfloat16_rn(x);
        __nv_bfloat16 l = __float2bfloat16_rn(x - __bfloat162float(h));
        const size_t o = (size_t)(n0 + nl) * D_IN + k0 + tx;
        g_wtbf[o] = h;
        g_wtbf[(size_t)N_QKV * D_IN + o] = l;
    }
}

// ================= Kernel 1: QKV GEMM (mma.sync bf16 split) =================
#define NSTAGE  3
#define ATILE_B 16384
#define STAGE_B 32768
#define GEMM_SMEM (NSTAGE * STAGE_B)

__global__ __launch_bounds__(256) void qkv_gemm_mma(const float* __restrict__ bias) {
    extern __shared__ char smem[];
    const uint32_t sb = smem_to_u32(smem);
    const int tid = threadIdx.x;
    const int lane = tid & 31, wid = tid >> 5;
    const int bm = blockIdx.y * 128;
    const int bn = blockIdx.x * 128;
    const int mw = (wid >> 2) * 64;
    const int nw = (wid & 3) * 32;

    auto load_stage = [&](int c) {
        const uint32_t st = sb + (uint32_t)(c % NSTAGE) * STAGE_B;
        const int koff = c * 32;
#pragma unroll
        for (int i = 0; i < 8; i++) {
            const int u = tid + i * 256;
            const int isB = u >> 10;
            const int row = (u >> 3) & 127;
            const int unit = u & 7;
            const int plane = unit >> 2, sub = unit & 3;
            const uint32_t dst = st + (uint32_t)isB * ATILE_B + row * 128 +
                                 (uint32_t)((unit ^ (row & 7)) << 4);
            const __nv_bfloat16* src = isB
                ? (g_wtbf + (size_t)plane * N_QKV * D_IN + (size_t)(bn + row) * D_IN + koff + sub * 8)
                : (g_xbf  + (size_t)plane * T_TOK * D_IN + (size_t)(bm + row) * D_IN + koff + sub * 8);
            cp16(dst, src);
        }
        cp_commit();
    };

    float acc[4][4][4];
#pragma unroll
    for (int i = 0; i < 4; i++)
#pragma unroll
        for (int j = 0; j < 4; j++)
#pragma unroll
            for (int t = 0; t < 4; t++) acc[i][j][t] = 0.f;

    const int a_r  = mw + (lane & 15);
    const int a_rx = a_r & 7;
    const int ua_hi_base = (lane >> 4);
    const int b_r  = nw + (lane & 7) + ((lane >> 4) << 3);
    const int b_rx = b_r & 7;
    const int ub_hi_base = ((lane >> 3) & 1);

    load_stage(0);
    load_stage(1);
    load_stage(2);

    for (int c = 0; c < 64; c++) {
        asm volatile("cp.async.wait_group 2;" ::: "memory");
        __syncthreads();

        const uint32_t st = sb + (uint32_t)(c % NSTAGE) * STAGE_B;
        const uint32_t stB = st + ATILE_B;
#pragma unroll
        for (int ks = 0; ks < 2; ks++) {
            const int ua = ks * 2 + ua_hi_base;
            const int ub = ks * 2 + ub_hi_base;
            uint32_t Ah[4][4], Al[4][4], Bh[2][4], Bl[2][4];
#pragma unroll
            for (int i = 0; i < 4; i++) {
                const uint32_t rowb = st + (uint32_t)(a_r + i * 16) * 128;
                ldsm4(Ah[i], rowb + (uint32_t)((ua ^ a_rx) << 4));
                ldsm4(Al[i], rowb + (uint32_t)(((ua + 4) ^ a_rx) << 4));
            }
#pragma unroll
            for (int p = 0; p < 2; p++) {
                const uint32_t rowb = stB + (uint32_t)(b_r + p * 16) * 128;
                ldsm4(Bh[p], rowb + (uint32_t)((ub ^ b_rx) << 4));
                ldsm4(Bl[p], rowb + (uint32_t)(((ub + 4) ^ b_rx) << 4));
            }
#pragma unroll
            for (int i = 0; i < 4; i++) {
#pragma unroll
                for (int j = 0; j < 4; j++) {
                    const uint32_t* bh = &Bh[j >> 1][(j & 1) * 2];
                    const uint32_t* bl = &Bl[j >> 1][(j & 1) * 2];
                    mma_bf16(acc[i][j], Ah[i], bh);
                    mma_bf16(acc[i][j], Ah[i], bl);
                    mma_bf16(acc[i][j], Al[i], bh);
                }
            }
        }
        __syncthreads();
        if (c + 3 < 64) load_stage(c + 3);
    }

    const int ml = bm + mw + (lane >> 2);
    const int nl0 = bn + nw + (lane & 3) * 2;
    const int region = (bn < 2048) ? 0 : (bn < 3072 ? 1 : 2);

#pragma unroll
    for (int j = 0; j < 4; j++) {
        const int n = nl0 + j * 8;
        const float b0 = __ldg(bias + n), b1 = __ldg(bias + n + 1);
#pragma unroll
        for (int i = 0; i < 4; i++) {
#pragma unroll
            for (int half = 0; half < 2; half++) {
                const int m = ml + i * 16 + half * 8;
                const float v0 = acc[i][j][half * 2 + 0] + b0;
                const float v1 = acc[i][j][half * 2 + 1] + b1;
                if (region == 0) {
                    float2 o = make_float2(fmaxf(v0, 0.f) * 0.08838834764831845f,
                                           fmaxf(v1, 0.f) * 0.08838834764831845f);
                    *(float2*)&g_q[(size_t)m * 2048 + n] = o;
                } else if (region == 1) {
                    const int cc = n - 2048;
                    float s0 = fminf(__fdividef(1.f, 1.f + __expf(-v0)), 0.95f);
                    float s1 = fminf(__fdividef(1.f, 1.f + __expf(-v1)), 0.95f);
                    *(float2*)&g_k[(size_t)m * 1024 + cc] = make_float2(s0, s1);
                    *(float2*)&g_g[(size_t)m * 1024 + cc] = make_float2(__logf(1.f - s0), __logf(1.f - s1));
                } else {
                    *(float2*)&g_v[(size_t)m * 1024 + (n - 3072)] = make_float2(v0, v1);
                }
            }
        }
    }
}

// ================= Kernel 2: chunked GLA scan (tensor-core) =================
// smem layout (bytes):
//  [0, 33792)        sBc: 64 x 132 fp32 (g -> cumsum staging)
//  [33792, +512)     s_R[128]
//  [34304, +512)     s_eR[128]
//  [34816, +512)     s_fb[128]
//  [35328, +20*8192) bf16 panels, each 64 rows x 64 bf16 cols (128B rows, SW128)
//   panel idx: bQe   0+plane*2+khalf   (GEMM1 A: q*e^Bc)
//              bQe2  4+plane*2+khalf   (GEMM2 A: q*e^(Bc-R))
//              bKd   8+plane*2+khalf   (GEMM2 B: k*e^(R-Bc); later kg)
//              bS   12+plane*2+rowhalf (state, [k][v])
//              bV   16+plane           ([j][v])
//              bA   18+plane           (masked intra matrix)
#define BC_OFF   0
#define R_OFF    33792
#define ER_OFF   34304
#define FB_OFF   34816
#define PAN_OFF  35328
#define PANEL(i) (PAN_OFF + (i) * 8192)
#define GLA_SMEM (PAN_OFF + 20 * 8192)
// swizzled byte offset within a panel: row r (0-63), bf16 col c (0-63)
#define POFF(r, c) ((r) * 128 + ((((c) >> 3) ^ ((r) & 7)) << 4) + (((c) & 7) * 2))
#define PADDR(pi, r, u) (sb + PANEL(pi) + (r) * 128 + ((((u) ^ ((r) & 7))) << 4))

__global__ __launch_bounds__(256) void gla_attn(const float* __restrict__ kvc,
                                                const int* __restrict__ sidx,
                                                float* __restrict__ out) {
    extern __shared__ char smem[];
    const uint32_t sb = smem_to_u32(smem);
    float* sBc = (float*)(smem + BC_OFF);
    float* sR  = (float*)(smem + R_OFF);
    float* sER = (float*)(smem + ER_OFF);
    float* sFB = (float*)(smem + FB_OFF);

    const int vh  = blockIdx.x;   // 0..1
    const int h   = blockIdx.y;   // 0..15
    const int b   = blockIdx.z;   // 0..3
    const int kvh = h >> 1;
    const int tid = threadIdx.x;
    const int lane = tid & 31, wid = tid >> 5;
    // output/A tiling: 4x2 warp grid
    const int mw = (wid >> 1) * 16;
    const int nw = (wid & 1) * 32;
    // state tiling: warp owns k rows [kw, kw+16)
    const int kw = wid * 16;
    const int skh = kw >> 6;        // bS row-half for state
    const int kwl = kw & 63;
    // ldmatrix lane patterns
    const int rA = lane & 15, sA_ = lane >> 4;                 // pattA / transB
    const int rB = (lane & 7) | ((lane >> 4) << 3);            // pattB / transA row
    const int sB_ = (lane >> 3) & 1;
    // fragment element coords
    const int fr = lane >> 2, fc = (lane & 3) * 2;

    // ---- init S (bf16 hi/lo) from kv_cache ----
    {
        const int slot = sidx[b];
        const float* Sg = kvc + ((size_t)slot * Hh + h) * DHh * DHh + vh * 64;
#pragma unroll
        for (int t = 0; t < 8; t++) {
            const int u = tid + t * 256;         // 0..2047 float4 groups
            const int k = u >> 4, v4 = (u & 15) << 2;
            float4 s4 = *(const float4*)(Sg + (size_t)k * DHh + v4);
            uint32_t h0 = bfpack(s4.x, s4.y), h1 = bfpack(s4.z, s4.w);
            float2 hf0 = bfunpack(h0), hf1 = bfunpack(h1);
            uint32_t l0 = bfpack(s4.x - hf0.x, s4.y - hf0.y);
            uint32_t l1 = bfpack(s4.z - hf1.x, s4.w - hf1.y);
            const int off = POFF(k & 63, v4);
            *(uint2*)(smem + PANEL(12 + (k >> 6)) + off) = make_uint2(h0, h1);
            *(uint2*)(smem + PANEL(12 + 2 + (k >> 6)) + off) = make_uint2(l0, l1);
        }
    }
    __syncthreads();

    const float* qbase = g_q + (size_t)b * Ll * 2048 + h * DHh;
    const float* kbase = g_k + (size_t)b * Ll * 1024 + kvh * DHh;
    const float* gbase = g_g + (size_t)b * Ll * 1024 + kvh * DHh;
    const float* vbase = g_v + (size_t)b * Ll * 1024 + kvh * DHh + vh * 64;
    float* obase = out + (size_t)b * Ll * 2048 + h * DHh + vh * 64;

    for (int ch = 0; ch < 32; ch++) {
        const size_t row0 = (size_t)ch * 64;

        // ---- phase A: load g tile into sBc ----
#pragma unroll
        for (int t = 0; t < 8; t++) {
            const int u = tid + t * 256;
            const int i = u >> 5, k4 = (u & 31) << 2;
            float4 gv = *(const float4*)(gbase + (row0 + i) * 1024 + k4);
            *(float4*)&sBc[i * 132 + k4] = gv;
        }
        __syncthreads();

        // ---- phase B: cumsum (two threads per k-column) ----
        if (tid < 128) {
            const int k = tid;
            float run = 0.f;
#pragma unroll
            for (int r = 0; r < 32; r++) {
                run += sBc[r * 132 + k];
                sBc[r * 132 + k] = run;
            }
            sR[k] = run;               // R = Bc[31]
            sER[k] = __expf(run);
        } else {
            const int k = tid - 128;
            float run = 0.f;
#pragma unroll
            for (int r = 32; r < 64; r++) {
                run += sBc[r * 132 + k];
                sBc[r * 132 + k] = run;  // local prefix L = Bc - R
            }
            sFB[k] = __expf(run);       // e^(b_last - R)
        }
        __syncthreads();

        // ---- phase C: exponential scalings -> bf16 hi/lo panels ----
#pragma unroll
        for (int t = 0; t < 8; t++) {
            const int u = tid + t * 256;
            const int i = u >> 5, k4 = (u & 31) << 2;
            float4 q4 = *(const float4*)(qbase + (row0 + i) * 2048 + k4);
            float4 kq = *(const float4*)(kbase + (row0 + i) * 1024 + k4);
            float qe[4], qe2[4], kd[4];
#pragma unroll
            for (int j = 0; j < 4; j++) {
                const int k = k4 + j;
                float st = sBc[i * 132 + k];
                float d = (i < 32) ? (st - sR[k]) : st;     // Bc - R
                float e1 = __expf(fminf(d, 85.f));
                float e2 = __expf(fminf(-d, 85.f));
                float qv = (j == 0 ? q4.x : j == 1 ? q4.y : j == 2 ? q4.z : q4.w);
                float kv = (j == 0 ? kq.x : j == 1 ? kq.y : j == 2 ? kq.z : kq.w);
                qe2[j] = qv * e1;
                qe[j]  = qe2[j] * sER[k];
                kd[j]  = kv * e2;
            }
            const int kh = k4 >> 6, c = k4 & 63;
            const int off = POFF(i, c);
            // qe -> bQe
            {
                uint32_t h0 = bfpack(qe[0], qe[1]), h1 = bfpack(qe[2], qe[3]);
                float2 f0 = bfunpack(h0), f1 = bfunpack(h1);
                uint32_t l0 = bfpack(qe[0] - f0.x, qe[1] - f0.y);
                uint32_t l1 = bfpack(qe[2] - f1.x, qe[3] - f1.y);
                *(uint2*)(smem + PANEL(0 + kh) + off) = make_uint2(h0, h1);
                *(uint2*)(smem + PANEL(2 + kh) + off) = make_uint2(l0, l1);
            }
            // qe2 -> bQe2
            {
                uint32_t h0 = bfpack(qe2[0], qe2[1]), h1 = bfpack(qe2[2], qe2[3]);
                float2 f0 = bfunpack(h0), f1 = bfunpack(h1);
                uint32_t l0 = bfpack(qe2[0] - f0.x, qe2[1] - f0.y);
                uint32_t l1 = bfpack(qe2[2] - f1.x, qe2[3] - f1.y);
                *(uint2*)(smem + PANEL(4 + kh) + off) = make_uint2(h0, h1);
                *(uint2*)(smem + PANEL(6 + kh) + off) = make_uint2(l0, l1);
            }
            // kd -> bKd
            {
                uint32_t h0 = bfpack(kd[0], kd[1]), h1 = bfpack(kd[2], kd[3]);
                float2 f0 = bfunpack(h0), f1 = bfunpack(h1);
                uint32_t l0 = bfpack(kd[0] - f0.x, kd[1] - f0.y);
                uint32_t l1 = bfpack(kd[2] - f1.x, kd[3] - f1.y);
                *(uint2*)(smem + PANEL(8 + kh) + off) = make_uint2(h0, h1);
                *(uint2*)(smem + PANEL(10 + kh) + off) = make_uint2(l0, l1);
            }
        }
        // v tile -> bV
#pragma unroll
        for (int t = 0; t < 4; t++) {
            const int u = tid + t * 256;
            const int i = u >> 4, v4 = (u & 15) << 2;
            float4 vv = *(const float4*)(vbase + (row0 + i) * 1024 + v4);
            uint32_t h0 = bfpack(vv.x, vv.y), h1 = bfpack(vv.z, vv.w);
            float2 f0 = bfunpack(h0), f1 = bfunpack(h1);
            uint32_t l0 = bfpack(vv.x - f0.x, vv.y - f0.y);
            uint32_t l1 = bfpack(vv.z - f1.x, vv.w - f1.y);
            const int off = POFF(i, v4);
            *(uint2*)(smem + PANEL(16) + off) = make_uint2(h0, h1);
            *(uint2*)(smem + PANEL(17) + off) = make_uint2(l0, l1);
        }
        __syncthreads();

        // ---- phase D: GEMM2 (A = Qe2 @ Kd^T), mask+store; GEMM1 (o = Qe @ S) ----
        float accO[4][4];
        {
            float acc2[4][4];
#pragma unroll
            for (int t = 0; t < 4; t++)
#pragma unroll
                for (int e = 0; e < 4; e++) acc2[t][e] = 0.f;
#pragma unroll
            for (int kk = 0; kk < 8; kk++) {
                const int kh = kk >> 2, u0 = (kk & 3) * 2;
                uint32_t Ah[4], Al[4];
                ldsm4(Ah, PADDR(4 + kh, mw + rA, u0 + sA_));
                ldsm4(Al, PADDR(6 + kh, mw + rA, u0 + sA_));
#pragma unroll
                for (int g = 0; g < 2; g++) {
                    uint32_t Bh[4], Bl[4];
                    const int rowb = nw + g * 16 + rB;
                    ldsm4(Bh, PADDR(8 + kh, rowb, u0 + sB_));
                    ldsm4(Bl, PADDR(10 + kh, rowb, u0 + sB_));
#pragma unroll
                    for (int n8 = 0; n8 < 2; n8++) {
                        float* d = acc2[g * 2 + n8];
                        mma_bf16(d, Ah, Bh + n8 * 2);
                        mma_bf16(d, Ah, Bl + n8 * 2);
                        mma_bf16(d, Al, Bh + n8 * 2);
                    }
                }
            }
            // mask + split-store A
#pragma unroll
            for (int t = 0; t < 4; t++) {
                const int j = nw + t * 8 + fc;
#pragma unroll
                for (int half = 0; half < 2; half++) {
                    const int i = mw + fr + half * 8;
                    float x = (j <= i) ? acc2[t][half * 2 + 0] : 0.f;
                    float y = (j + 1 <= i) ? acc2[t][half * 2 + 1] : 0.f;
                    uint32_t hb = bfpack(x, y);
                    float2 hf = bfunpack(hb);
                    uint32_t lb = bfpack(x - hf.x, y - hf.y);
                    const int off = POFF(i, j);
                    *(uint32_t*)(smem + PANEL(18) + off) = hb;
                    *(uint32_t*)(smem + PANEL(19) + off) = lb;
                }
            }
            // GEMM1: o = Qe @ S
#pragma unroll
            for (int t = 0; t < 4; t++)
#pragma unroll
                for (int e = 0; e < 4; e++) accO[t][e] = 0.f;
#pragma unroll
            for (int kk = 0; kk < 8; kk++) {
                const int kh = kk >> 2, u0 = (kk & 3) * 2;
                uint32_t Ah[4], Al[4];
                ldsm4(Ah, PADDR(0 + kh, mw + rA, u0 + sA_));
                ldsm4(Al, PADDR(2 + kh, mw + rA, u0 + sA_));
                const int rowS = (kk & 3) * 16 + rA;
#pragma unroll
                for (int g = 0; g < 2; g++) {
                    const int un = (nw >> 3) + g * 2 + sA_;
                    uint32_t Bh[4], Bl[4];
                    ldsm4t(Bh, PADDR(12 + kh, rowS, un));
                    ldsm4t(Bl, PADDR(14 + kh, rowS, un));
#pragma unroll
                    for (int n8 = 0; n8 < 2; n8++) {
                        float* d = accO[g * 2 + n8];
                        mma_bf16(d, Ah, Bh + n8 * 2);
                        mma_bf16(d, Ah, Bl + n8 * 2);
                        mma_bf16(d, Al, Bh + n8 * 2);
                    }
                }
            }
        }
        __syncthreads();

        // ---- phase E: kg = kd * fb (rescale bKd panels in place) ----
#pragma unroll
        for (int t = 0; t < 16; t++) {
            const int u = tid + t * 256;       // 4096 bf16-pairs
            const int i = u >> 6, k = (u & 63) * 2;
            const int kh = k >> 6;
            const int off = POFF(i, k & 63);
            uint32_t hb = *(uint32_t*)(smem + PANEL(8 + kh) + off);
            uint32_t lb = *(uint32_t*)(smem + PANEL(10 + kh) + off);
            float2 hf = bfunpack(hb), lf = bfunpack(lb);
            float f0 = (hf.x + lf.x) * sFB[k];
            float f1 = (hf.y + lf.y) * sFB[k + 1];
            uint32_t nh = bfpack(f0, f1);
            float2 nf = bfunpack(nh);
            uint32_t nl = bfpack(f0 - nf.x, f1 - nf.y);
            *(uint32_t*)(smem + PANEL(8 + kh) + off) = nh;
            *(uint32_t*)(smem + PANEL(10 + kh) + off) = nl;
        }
        __syncthreads();

        // ---- phase F: GEMM3 (o += A @ V); write o; state update ----
#pragma unroll
        for (int kk = 0; kk < 4; kk++) {
            const int u0 = kk * 2;
            uint32_t Ah[4], Al[4];
            ldsm4(Ah, PADDR(18, mw + rA, u0 + sA_));
            ldsm4(Al, PADDR(19, mw + rA, u0 + sA_));
            const int rowV = kk * 16 + rA;
#pragma unroll
            for (int g = 0; g < 2; g++) {
                const int un = (nw >> 3) + g * 2 + sA_;
                uint32_t Bh[4], Bl[4];
                ldsm4t(Bh, PADDR(16, rowV, un));
                ldsm4t(Bl, PADDR(17, rowV, un));
#pragma unroll
                for (int n8 = 0; n8 < 2; n8++) {
                    float* d = accO[g * 2 + n8];
                    mma_bf16(d, Ah, Bh + n8 * 2);
                    mma_bf16(d, Ah, Bl + n8 * 2);
                    mma_bf16(d, Al, Bh + n8 * 2);
                }
            }
        }
        // write o
#pragma unroll
        for (int t = 0; t < 4; t++) {
            const int v = nw + t * 8 + fc;
#pragma unroll
            for (int half = 0; half < 2; half++) {
                const int i = mw + fr + half * 8;
                *(float2*)(obase + (row0 + i) * 2048 + v) =
                    make_float2(accO[t][half * 2], accO[t][half * 2 + 1]);
            }
        }
        // state update: S = S*e^(b_last) + Kg^T @ V
        {
            float accS[8][4];
#pragma unroll
            for (int half = 0; half < 2; half++) {
                const int krow = kw + fr + half * 8;
                const float ebl = sER[krow] * sFB[krow];
#pragma unroll
                for (int t = 0; t < 8; t++) {
                    const int v = t * 8 + fc;
                    const int off = POFF(krow & 63, v);
                    float2 hf = bfunpack(*(uint32_t*)(smem + PANEL(12 + skh) + off));
                    float2 lf = bfunpack(*(uint32_t*)(smem + PANEL(14 + skh) + off));
                    accS[t][half * 2 + 0] = (hf.x + lf.x) * ebl;
                    accS[t][half * 2 + 1] = (hf.y + lf.y) * ebl;
                }
            }
#pragma unroll
            for (int kk = 0; kk < 4; kk++) {
                const int rowJ = rB + kk * 16;
                const int unM = (kwl >> 3) + sB_;
                uint32_t Ah[4], Al[4];
                ldsm4t(Ah, PADDR(8 + skh, rowJ, unM));
                ldsm4t(Al, PADDR(10 + skh, rowJ, unM));
                const int rowV = kk * 16 + rA;
#pragma unroll
                for (int g = 0; g < 4; g++) {
                    const int un = g * 2 + sA_;
                    uint32_t Bh[4], Bl[4];
                    ldsm4t(Bh, PADDR(16, rowV, un));
                    ldsm4t(Bl, PADDR(17, rowV, un));
#pragma unroll
                    for (int n8 = 0; n8 < 2; n8++) {
                        float* d = accS[g * 2 + n8];
                        mma_bf16(d, Ah, Bh + n8 * 2);
                        mma_bf16(d, Ah, Bl + n8 * 2);
                        mma_bf16(d, Al, Bh + n8 * 2);
                    }
                }
            }
            // store S back (hi/lo)
#pragma unroll
            for (int half = 0; half < 2; half++) {
                const int krow = kw + fr + half * 8;
#pragma unroll
                for (int t = 0; t < 8; t++) {
                    const int v = t * 8 + fc;
                    float x = accS[t][half * 2 + 0], y = accS[t][half * 2 + 1];
                    uint32_t hb = bfpack(x, y);
                    float2 hf = bfunpack(hb);
                    uint32_t lb = bfpack(x - hf.x, y - hf.y);
                    const int off = POFF(krow & 63, v);
                    *(uint32_t*)(smem + PANEL(12 + skh) + off) = hb;
                    *(uint32_t*)(smem + PANEL(14 + skh) + off) = lb;
                }
            }
        }
        __syncthreads();
    }
}

// ---------------- launch ----------------
extern "C" void kernel_launch(void* const* d_in, const int* in_sizes, int n_in,
                              void* d_out, int out_size) {
    const float* X    = (const float*)d_in[0];
    const float* W    = (const float*)d_in[1];
    const float* bias = (const float*)d_in[2];
    const float* kvc  = (const float*)d_in[3];
    const int*   sidx = (const int*)d_in[4];
    float* out = (float*)d_out;

    prep_x<<<(T_TOK * D_IN) / (256 * 4), 256>>>(X);
    prep_w<<<dim3(N_QKV / 32, D_IN / 32), 256>>>(W);

    cudaFuncSetAttribute(qkv_gemm_mma, cudaFuncAttributeMaxDynamicSharedMemorySize, GEMM_SMEM);
    dim3 gg(N_QKV / 128, T_TOK / 128);
    qkv_gemm_mma<<<gg, 256, GEMM_SMEM>>>(bias);

    cudaFuncSetAttribute(gla_attn, cudaFuncAttributeMaxDynamicSharedMemorySize, GLA_SMEM);
    dim3 ga(2, Hh, Bb);
    gla_attn<<<ga, 256, GLA_SMEM>>>(kvc, sidx, out);
}